// round 11
// baseline (speedup 1.0000x reference)
#include <cuda_runtime.h>
#include <cuda_fp16.h>
#include <mma.h>
#include <math.h>
#include <stdint.h>

using namespace nvcuda;

// Problem constants
#define CHUNKS     8
#define CSIZE      512
#define DIM        4096
#define NROWS      16384
#define INV_TEMP   (1.0f / 0.15f)
#define SINK_ITERS 5

// Scratch (device globals — no runtime allocation allowed)
__device__ float  g_p[64];                             // 8x8 chunk perm
__device__ float  g_r[CHUNKS * CSIZE];                 // row offsets (16 KB)
__device__ float  g_c[CHUNKS * CSIZE];                 // col offsets (16 KB)
__device__ __half g_qh[CHUNKS * CSIZE * CSIZE];        // 4 MB   Q fp16
__device__ __half g_yh[(size_t)NROWS * DIM];           // 128 MB Y fp16

// ---------------------------------------------------------------------------
// Sinkhorn on 8x8 chunk logits
// ---------------------------------------------------------------------------
__global__ void sinkhorn_chunk_kernel(const float* __restrict__ logits,
                                      float* __restrict__ p_out) {
    __shared__ float s[64];
    int t = threadIdx.x;
    int r = t >> 3;
    int c = t & 7;
    float v = logits[t] * INV_TEMP;

    for (int it = 0; it < SINK_ITERS; ++it) {
        s[t] = v;
        __syncthreads();
        float mx = -1e30f;
        #pragma unroll
        for (int j = 0; j < 8; ++j) mx = fmaxf(mx, s[r * 8 + j]);
        float sm = 0.0f;
        #pragma unroll
        for (int j = 0; j < 8; ++j) sm += expf(s[r * 8 + j] - mx);
        v -= mx + logf(sm);
        __syncthreads();

        s[t] = v;
        __syncthreads();
        mx = -1e30f;
        #pragma unroll
        for (int j = 0; j < 8; ++j) mx = fmaxf(mx, s[j * 8 + c]);
        sm = 0.0f;
        #pragma unroll
        for (int j = 0; j < 8; ++j) sm += expf(s[j * 8 + c] - mx);
        v -= mx + logf(sm);
        __syncthreads();
    }
    p_out[t] = expf(v);
}

// ---------------------------------------------------------------------------
// Intra sinkhorn, vector form: r_i = LSE_j(L_ij - c_j), L = logits * INV_TEMP.
// Warp per row, shuffle reductions. Grid = 1024 x 128.
// ---------------------------------------------------------------------------
__global__ void rvec_kernel(const float* __restrict__ in,
                            const float* __restrict__ c,
                            float* __restrict__ r, int first) {
    int row  = blockIdx.x * 4 + (threadIdx.x >> 5);
    int lane = threadIdx.x & 31;
    const float4* p  = (const float4*)(in + (size_t)row * CSIZE);
    const float4* cp = (const float4*)(c + (size_t)(row >> 9) * CSIZE);

    float4 v[4];
    float mx = -1e30f;
    #pragma unroll
    for (int i = 0; i < 4; ++i) {
        float4 t = p[lane + i * 32];
        t.x *= INV_TEMP; t.y *= INV_TEMP; t.z *= INV_TEMP; t.w *= INV_TEMP;
        if (!first) {
            float4 cv = cp[lane + i * 32];
            t.x -= cv.x; t.y -= cv.y; t.z -= cv.z; t.w -= cv.w;
        }
        v[i] = t;
        mx = fmaxf(mx, fmaxf(fmaxf(t.x, t.y), fmaxf(t.z, t.w)));
    }
    #pragma unroll
    for (int off = 16; off > 0; off >>= 1)
        mx = fmaxf(mx, __shfl_xor_sync(0xFFFFFFFFu, mx, off));

    float sm = 0.0f;
    #pragma unroll
    for (int i = 0; i < 4; ++i) {
        sm += expf(v[i].x - mx) + expf(v[i].y - mx)
            + expf(v[i].z - mx) + expf(v[i].w - mx);
    }
    #pragma unroll
    for (int off = 16; off > 0; off >>= 1)
        sm += __shfl_xor_sync(0xFFFFFFFFu, sm, off);

    if (lane == 0) r[row] = mx + logf(sm);
}

// ---------------------------------------------------------------------------
// Intra sinkhorn, vector form: c_j = LSE_i(L_ij - r_i).
// Grid = 8 chunks * 16 colgroups, 512 threads (16 rowgroups x 32 cols).
// Final pass also emits qh = exp(L - r - c) as fp16.
// ---------------------------------------------------------------------------
__global__ void cvec_kernel(const float* __restrict__ in,
                            const float* __restrict__ r,
                            float* __restrict__ c,
                            __half* __restrict__ qh, int final_pass) {
    int chunk = blockIdx.x >> 4;
    int colbase = (blockIdx.x & 15) * 32;
    int t = threadIdx.x;
    int col = t & 31;
    int rg  = t >> 5;                 // 0..15
    size_t base_i = (size_t)chunk * CSIZE * CSIZE + colbase + col;
    const float* base  = in + base_i;
    const float* rbase = r + chunk * CSIZE;

    __shared__ float red[16][32];

    float mx = -1e30f;
    for (int row = rg; row < CSIZE; row += 16)
        mx = fmaxf(mx, base[(size_t)row * CSIZE] * INV_TEMP - rbase[row]);
    red[rg][col] = mx;
    __syncthreads();
    if (rg == 0) {
        float m = red[0][col];
        #pragma unroll
        for (int j = 1; j < 16; ++j) m = fmaxf(m, red[j][col]);
        red[0][col] = m;
    }
    __syncthreads();
    mx = red[0][col];
    __syncthreads();

    float sm = 0.0f;
    for (int row = rg; row < CSIZE; row += 16)
        sm += expf(base[(size_t)row * CSIZE] * INV_TEMP - rbase[row] - mx);
    red[rg][col] = sm;
    __syncthreads();
    if (rg == 0) {
        float s = red[0][col];
        #pragma unroll
        for (int j = 1; j < 16; ++j) s += red[j][col];
        red[0][col] = s;
    }
    __syncthreads();
    float lse = mx + logf(red[0][col]);

    if (rg == 0) c[chunk * CSIZE + colbase + col] = lse;

    if (final_pass) {
        __half* qbase = qh + base_i;
        for (int row = rg; row < CSIZE; row += 16)
            qbase[(size_t)row * CSIZE] = __float2half(
                expf(base[(size_t)row * CSIZE] * INV_TEMP - rbase[row] - lse));
    }
}

// ---------------------------------------------------------------------------
// Chunk mix producing fp16: y = P @ x per (b, d)
// ---------------------------------------------------------------------------
__global__ void mix_half_kernel(const float* __restrict__ x,
                                __half* __restrict__ yh,
                                const float* __restrict__ P) {
    __shared__ float p[64];
    if (threadIdx.x < 64) p[threadIdx.x] = P[threadIdx.x];
    __syncthreads();

    int idx = blockIdx.x * blockDim.x + threadIdx.x;
    int b  = idx >> 7;
    int d4 = idx & 127;

    const float4* xb = (const float4*)(x + (size_t)b * DIM) + d4;

    float4 xv[8];
    #pragma unroll
    for (int j = 0; j < 8; ++j) xv[j] = xb[(size_t)j * 128];

    #pragma unroll
    for (int i = 0; i < 8; ++i) {
        float4 acc = make_float4(0.f, 0.f, 0.f, 0.f);
        #pragma unroll
        for (int j = 0; j < 8; ++j) {
            float w = p[i * 8 + j];
            acc.x += w * xv[j].x;
            acc.y += w * xv[j].y;
            acc.z += w * xv[j].z;
            acc.w += w * xv[j].w;
        }
        __half2 h01 = __floats2half2_rn(acc.x, acc.y);
        __half2 h23 = __floats2half2_rn(acc.z, acc.w);
        size_t e = (size_t)b * DIM + (size_t)i * CSIZE + (size_t)d4 * 4;  // even
        ((__half2*)yh)[e >> 1]       = h01;
        ((__half2*)yh)[(e >> 1) + 1] = h23;
    }
}

// ---------------------------------------------------------------------------
// WMMA (HMMA) GEMM, fp16 in / fp32 accum: per CTA 128x128 tile, K = 512.
// Double-buffered cp.async, 8 warps (2M x 4N), warp tile 64x32.
// (Measured at the legacy-HMMA issue ceiling — do not touch.)
// ---------------------------------------------------------------------------
#define LDS_PAD 40          // padded row stride (elems): 80 B, multiple of 16 B
#define NKITER  16          // 512 / 32

__device__ __forceinline__ void cp16(uint32_t dst, const void* src) {
    asm volatile("cp.async.cg.shared.global [%0], [%1], 16;" :: "r"(dst), "l"(src));
}

__global__ __launch_bounds__(256, 2)
void wmma_gemm_kernel(const __half* __restrict__ yh,
                      const __half* __restrict__ qh,
                      float* __restrict__ out) {
    __shared__ __half sA[2][128 * LDS_PAD];
    __shared__ __half sB[2][128 * LDS_PAD];

    const int c  = blockIdx.z;
    const int m0 = blockIdx.y * 128;
    const int n0 = blockIdx.x * 128;
    const int tid = threadIdx.x;
    const int wid = tid >> 5;
    const int wm  = wid & 1;       // 0..1  -> 64-row slab
    const int wn  = wid >> 1;      // 0..3  -> 32-col slab

    wmma::fragment<wmma::accumulator, 16, 16, 16, float> acc[4][2];
    #pragma unroll
    for (int i = 0; i < 4; ++i)
        #pragma unroll
        for (int j = 0; j < 2; ++j) wmma::fill_fragment(acc[i][j], 0.0f);

    // per-thread load assignment: 512 x 16B chunks per tile, 2 per thread
    const int r0  = (tid + 0)   >> 2;
    const int cb0 = (tid + 0)   & 3;
    const int r1  = (tid + 256) >> 2;
    const int cb1 = (tid + 256) & 3;

    uint32_t sA0[2], sA1[2], sB0[2], sB1[2];
    #pragma unroll
    for (int b = 0; b < 2; ++b) {
        sA0[b] = (uint32_t)__cvta_generic_to_shared(&sA[b][r0 * LDS_PAD + cb0 * 8]);
        sA1[b] = (uint32_t)__cvta_generic_to_shared(&sA[b][r1 * LDS_PAD + cb1 * 8]);
        sB0[b] = (uint32_t)__cvta_generic_to_shared(&sB[b][r0 * LDS_PAD + cb0 * 8]);
        sB1[b] = (uint32_t)__cvta_generic_to_shared(&sB[b][r1 * LDS_PAD + cb1 * 8]);
    }

    const __half* Abase = yh + (size_t)m0 * DIM + (size_t)c * CSIZE;
    const __half* Bbase = qh + (size_t)c * CSIZE * CSIZE + (size_t)n0 * CSIZE;

    auto issue_loads = [&](int i, int buf) {
        int kk = i << 5;
        const __half* A = Abase + kk;
        const __half* B = Bbase + kk;
        cp16(sA0[buf], A + (size_t)r0 * DIM + cb0 * 8);
        cp16(sA1[buf], A + (size_t)r1 * DIM + cb1 * 8);
        cp16(sB0[buf], B + (size_t)r0 * CSIZE + cb0 * 8);
        cp16(sB1[buf], B + (size_t)r1 * CSIZE + cb1 * 8);
        asm volatile("cp.async.commit_group;" ::: "memory");
    };

    issue_loads(0, 0);

    for (int i = 0; i < NKITER; ++i) {
        int s = i & 1;
        asm volatile("cp.async.wait_group 0;" ::: "memory");
        __syncthreads();

        if (i < NKITER - 1) issue_loads(i + 1, s ^ 1);

        #pragma unroll
        for (int k2 = 0; k2 < 2; ++k2) {
            wmma::fragment<wmma::matrix_a, 16, 16, 16, __half, wmma::row_major> af[4];
            wmma::fragment<wmma::matrix_b, 16, 16, 16, __half, wmma::col_major> bf[2];
            #pragma unroll
            for (int mi = 0; mi < 4; ++mi)
                wmma::load_matrix_sync(af[mi],
                    &sA[s][(wm * 64 + mi * 16) * LDS_PAD + k2 * 16], LDS_PAD);
            #pragma unroll
            for (int nj = 0; nj < 2; ++nj)
                wmma::load_matrix_sync(bf[nj],
                    &sB[s][(wn * 32 + nj * 16) * LDS_PAD + k2 * 16], LDS_PAD);
            #pragma unroll
            for (int mi = 0; mi < 4; ++mi)
                #pragma unroll
                for (int nj = 0; nj < 2; ++nj)
                    wmma::mma_sync(acc[mi][nj], af[mi], bf[nj], acc[mi][nj]);
        }
        __syncthreads();
    }

    // epilogue: direct store to out
    #pragma unroll
    for (int mi = 0; mi < 4; ++mi) {
        #pragma unroll
        for (int nj = 0; nj < 2; ++nj) {
            float* dst = out + (size_t)(m0 + wm * 64 + mi * 16) * DIM
                             + (size_t)c * CSIZE + n0 + wn * 32 + nj * 16;
            wmma::store_matrix_sync(dst, acc[mi][nj], DIM, wmma::mem_row_major);
        }
    }
}

// ---------------------------------------------------------------------------
// Launch: fork intra-sinkhorn onto a side stream, overlap with chunk mix.
//   s0: chunk_sinkhorn ──┬─> mix ─────────┬─> GEMM
//   s1 (fork):           └─> 10 LSE passes┘
// ---------------------------------------------------------------------------
extern "C" void kernel_launch(void* const* d_in, const int* in_sizes, int n_in,
                              void* d_out, int out_size) {
    const float* x            = (const float*)d_in[0];
    const float* chunk_logits = (const float*)d_in[1];
    const float* intra_logits = (const float*)d_in[2];
    float*       out          = (float*)d_out;

    float*  p;  cudaGetSymbolAddress((void**)&p,  g_p);
    float*  rv; cudaGetSymbolAddress((void**)&rv, g_r);
    float*  cv; cudaGetSymbolAddress((void**)&cv, g_c);
    __half* qh; cudaGetSymbolAddress((void**)&qh, g_qh);
    __half* yh; cudaGetSymbolAddress((void**)&yh, g_yh);

    cudaStream_t s1;
    cudaStreamCreateWithFlags(&s1, cudaStreamNonBlocking);
    cudaEvent_t eFork, eJoin;
    cudaEventCreateWithFlags(&eFork, cudaEventDisableTiming);
    cudaEventCreateWithFlags(&eJoin, cudaEventDisableTiming);

    // s0: 8x8 chunk sinkhorn (mix depends on it)
    sinkhorn_chunk_kernel<<<1, 64>>>(chunk_logits, p);

    // fork s1 from s0
    cudaEventRecord(eFork, 0);
    cudaStreamWaitEvent(s1, eFork, 0);

    // s1: intra sinkhorn in vector form (independent of chunk perm / mix)
    for (int it = 0; it < SINK_ITERS; ++it) {
        rvec_kernel<<<CHUNKS * CSIZE / 4, 128, 0, s1>>>(intra_logits, cv, rv,
                                                        it == 0);
        cvec_kernel<<<CHUNKS * 16, 512, 0, s1>>>(intra_logits, rv, cv, qh,
                                                 (it == SINK_ITERS - 1) ? 1 : 0);
    }
    cudaEventRecord(eJoin, s1);

    // s0: chunk mix -> fp16 Y (overlaps with s1)
    mix_half_kernel<<<(NROWS * 128) / 256, 256>>>(x, yh, p);

    // join: GEMM needs both qh (s1) and yh (s0)
    cudaStreamWaitEvent(0, eJoin, 0);
    dim3 grid(4, NROWS / 128, CHUNKS);
    wmma_gemm_kernel<<<grid, 256>>>(yh, qh, out);

    cudaEventDestroy(eFork);
    cudaEventDestroy(eJoin);
    cudaStreamDestroy(s1);
}

// round 12
// speedup vs baseline: 1.0138x; 1.0138x over previous
#include <cuda_runtime.h>
#include <cuda_fp16.h>
#include <mma.h>
#include <math.h>
#include <stdint.h>

using namespace nvcuda;

// Problem constants
#define CHUNKS     8
#define CSIZE      512
#define DIM        4096
#define NROWS      16384
#define INV_TEMP   (1.0f / 0.15f)
#define SINK_ITERS 5

#define NB          8                     // sinkhorn blocks per chunk
#define SINK_BLOCKS (CHUNKS * NB)         // 64

// Scratch (device globals — no runtime allocation allowed)
__device__ float    g_p[64];                          // 8x8 chunk perm
__device__ float    g_r[CHUNKS * CSIZE];              // row offsets
__device__ float    g_c[CHUNKS * CSIZE];              // col offsets
__device__ unsigned g_barc[CHUNKS];                   // barrier arrive counters
__device__ unsigned g_barg[CHUNKS];                   // barrier generations
__device__ __half   g_qh[CHUNKS * CSIZE * CSIZE];     // 4 MB   Q fp16
__device__ __half   g_yh[(size_t)NROWS * DIM];        // 128 MB Y fp16

// ---------------------------------------------------------------------------
// Sinkhorn on 8x8 chunk logits
// ---------------------------------------------------------------------------
__global__ void sinkhorn_chunk_kernel(const float* __restrict__ logits,
                                      float* __restrict__ p_out) {
    __shared__ float s[64];
    int t = threadIdx.x;
    int r = t >> 3;
    int c = t & 7;
    float v = logits[t] * INV_TEMP;

    for (int it = 0; it < SINK_ITERS; ++it) {
        s[t] = v;
        __syncthreads();
        float mx = -1e30f;
        #pragma unroll
        for (int j = 0; j < 8; ++j) mx = fmaxf(mx, s[r * 8 + j]);
        float sm = 0.0f;
        #pragma unroll
        for (int j = 0; j < 8; ++j) sm += expf(s[r * 8 + j] - mx);
        v -= mx + logf(sm);
        __syncthreads();

        s[t] = v;
        __syncthreads();
        mx = -1e30f;
        #pragma unroll
        for (int j = 0; j < 8; ++j) mx = fmaxf(mx, s[j * 8 + c]);
        sm = 0.0f;
        #pragma unroll
        for (int j = 0; j < 8; ++j) sm += expf(s[j * 8 + c] - mx);
        v -= mx + logf(sm);
        __syncthreads();
    }
    p_out[t] = expf(v);
}

// ---------------------------------------------------------------------------
// Per-chunk inter-block barrier (generation-counting, CG grid.sync pattern).
// All NB blocks of a chunk are resident (bid 0..63 dispatched first).
// ---------------------------------------------------------------------------
__device__ __forceinline__ void chunk_barrier(int chunk, unsigned* sgen) {
    __syncthreads();
    if (threadIdx.x == 0) {
        __threadfence();
        unsigned g = *sgen;
        if (atomicAdd(&g_barc[chunk], 1) == NB - 1) {
            g_barc[chunk] = 0;
            __threadfence();
            atomicExch(&g_barg[chunk], g + 1);
        } else {
            while (atomicAdd(&g_barg[chunk], 0) <= g) __nanosleep(64);
        }
        *sgen = g + 1;
    }
    __syncthreads();
}

// ---------------------------------------------------------------------------
// Fused pre-GEMM kernel.
//   blocks [0, 64):  persistent intra-sinkhorn, 8 blocks/chunk, vector form:
//                      r_i = LSE_j(L_ij - c_j); c_j = LSE_i(L_ij - r_i)
//                    (no max-shift: args bounded in [-8, 1]); final pass
//                    emits qh = exp(L - r - c) in fp16.
//   blocks [64, ..): chunk mix y = P @ x -> fp16 yh.
// The two families are independent -> structural overlap, one launch.
// ---------------------------------------------------------------------------
__global__ __launch_bounds__(512, 2)
void fused_pre_kernel(const float* __restrict__ intra,
                      const float* __restrict__ x,
                      const float* __restrict__ P,
                      __half* __restrict__ qh,
                      __half* __restrict__ yh,
                      float* __restrict__ rg_, float* __restrict__ cg_) {
    __shared__ float smem[512];
    __shared__ unsigned sgen;

    if (blockIdx.x < SINK_BLOCKS) {
        // ------------------ intra-sinkhorn lane ------------------
        const int chunk = blockIdx.x >> 3;
        const int sub   = blockIdx.x & 7;
        const int tid   = threadIdx.x;
        const int warp  = tid >> 5;
        const int lane  = tid & 31;
        const float* L = intra + (size_t)chunk * CSIZE * CSIZE;
        float* rv = rg_ + chunk * CSIZE;
        float* cv = cg_ + chunk * CSIZE;

        if (tid == 0) sgen = atomicAdd(&g_barg[chunk], 0);
        __syncthreads();

        for (int it = 0; it < SINK_ITERS; ++it) {
            // r-pass: rows [sub*64, sub*64+64), 4 rows per warp
            #pragma unroll
            for (int k = 0; k < 4; ++k) {
                int row = sub * 64 + warp * 4 + k;
                const float4* lp = (const float4*)(L + (size_t)row * CSIZE);
                float s = 0.0f;
                #pragma unroll
                for (int q = 0; q < 4; ++q) {
                    float4 t = lp[lane + q * 32];
                    if (it > 0) {
                        float4 cc = ((const float4*)cv)[lane + q * 32];
                        s += __expf(t.x * INV_TEMP - cc.x)
                           + __expf(t.y * INV_TEMP - cc.y)
                           + __expf(t.z * INV_TEMP - cc.z)
                           + __expf(t.w * INV_TEMP - cc.w);
                    } else {
                        s += __expf(t.x * INV_TEMP) + __expf(t.y * INV_TEMP)
                           + __expf(t.z * INV_TEMP) + __expf(t.w * INV_TEMP);
                    }
                }
                #pragma unroll
                for (int o = 16; o > 0; o >>= 1)
                    s += __shfl_xor_sync(0xFFFFFFFFu, s, o);
                if (lane == 0) rv[row] = __logf(s);
            }
            chunk_barrier(chunk, &sgen);

            // c-pass: cols [sub*64, sub*64+64), 8 rowgroups x 64 cols
            {
                int col = sub * 64 + (tid & 63);
                int rgp = tid >> 6;                  // 0..7
                float s = 0.0f;
                for (int row = rgp; row < CSIZE; row += 8)
                    s += __expf(L[(size_t)row * CSIZE + col] * INV_TEMP - rv[row]);
                smem[tid] = s;
                __syncthreads();
                if (tid < 64) {
                    float tot = smem[tid];
                    #pragma unroll
                    for (int j = 1; j < 8; ++j) tot += smem[tid + j * 64];
                    cv[sub * 64 + tid] = __logf(tot);
                }
                __syncthreads();
            }
            chunk_barrier(chunk, &sgen);
        }

        // emit qh = exp(L*invT - r - c), rows [sub*64, +64), coalesced by row
        float cj = cv[tid];
        __half* qbase = qh + (size_t)chunk * CSIZE * CSIZE;
        for (int row = sub * 64; row < sub * 64 + 64; ++row) {
            float rr = rv[row];
            qbase[(size_t)row * CSIZE + tid] = __float2half(
                __expf(L[(size_t)row * CSIZE + tid] * INV_TEMP - rr - cj));
        }
    } else {
        // ------------------ chunk-mix lane ------------------
        if (threadIdx.x < 64) smem[threadIdx.x] = P[threadIdx.x];
        __syncthreads();

        int id = (blockIdx.x - SINK_BLOCKS) * 512 + threadIdx.x;
        int b  = id >> 7;
        int d4 = id & 127;

        const float4* xb = (const float4*)(x + (size_t)b * DIM) + d4;

        float4 xv[8];
        #pragma unroll
        for (int j = 0; j < 8; ++j) xv[j] = xb[(size_t)j * 128];

        #pragma unroll
        for (int i = 0; i < 8; ++i) {
            float4 acc = make_float4(0.f, 0.f, 0.f, 0.f);
            #pragma unroll
            for (int j = 0; j < 8; ++j) {
                float w = smem[i * 8 + j];
                acc.x += w * xv[j].x;
                acc.y += w * xv[j].y;
                acc.z += w * xv[j].z;
                acc.w += w * xv[j].w;
            }
            __half2 h01 = __floats2half2_rn(acc.x, acc.y);
            __half2 h23 = __floats2half2_rn(acc.z, acc.w);
            size_t e = (size_t)b * DIM + (size_t)i * CSIZE + (size_t)d4 * 4;
            ((__half2*)yh)[e >> 1]       = h01;
            ((__half2*)yh)[(e >> 1) + 1] = h23;
        }
    }
}

// ---------------------------------------------------------------------------
// WMMA (HMMA) GEMM, fp16 in / fp32 accum: per CTA 128x128 tile, K = 512.
// Double-buffered cp.async, 8 warps (2M x 4N), warp tile 64x32.
// (Measured at the legacy-HMMA issue ceiling — do not touch.)
// ---------------------------------------------------------------------------
#define LDS_PAD 40
#define NKITER  16

__device__ __forceinline__ void cp16(uint32_t dst, const void* src) {
    asm volatile("cp.async.cg.shared.global [%0], [%1], 16;" :: "r"(dst), "l"(src));
}

__global__ __launch_bounds__(256, 2)
void wmma_gemm_kernel(const __half* __restrict__ yh,
                      const __half* __restrict__ qh,
                      float* __restrict__ out) {
    __shared__ __half sA[2][128 * LDS_PAD];
    __shared__ __half sB[2][128 * LDS_PAD];

    const int c  = blockIdx.z;
    const int m0 = blockIdx.y * 128;
    const int n0 = blockIdx.x * 128;
    const int tid = threadIdx.x;
    const int wid = tid >> 5;
    const int wm  = wid & 1;
    const int wn  = wid >> 1;

    wmma::fragment<wmma::accumulator, 16, 16, 16, float> acc[4][2];
    #pragma unroll
    for (int i = 0; i < 4; ++i)
        #pragma unroll
        for (int j = 0; j < 2; ++j) wmma::fill_fragment(acc[i][j], 0.0f);

    const int r0  = (tid + 0)   >> 2;
    const int cb0 = (tid + 0)   & 3;
    const int r1  = (tid + 256) >> 2;
    const int cb1 = (tid + 256) & 3;

    uint32_t sA0[2], sA1[2], sB0[2], sB1[2];
    #pragma unroll
    for (int b = 0; b < 2; ++b) {
        sA0[b] = (uint32_t)__cvta_generic_to_shared(&sA[b][r0 * LDS_PAD + cb0 * 8]);
        sA1[b] = (uint32_t)__cvta_generic_to_shared(&sA[b][r1 * LDS_PAD + cb1 * 8]);
        sB0[b] = (uint32_t)__cvta_generic_to_shared(&sB[b][r0 * LDS_PAD + cb0 * 8]);
        sB1[b] = (uint32_t)__cvta_generic_to_shared(&sB[b][r1 * LDS_PAD + cb1 * 8]);
    }

    const __half* Abase = yh + (size_t)m0 * DIM + (size_t)c * CSIZE;
    const __half* Bbase = qh + (size_t)c * CSIZE * CSIZE + (size_t)n0 * CSIZE;

    auto issue_loads = [&](int i, int buf) {
        int kk = i << 5;
        const __half* A = Abase + kk;
        const __half* B = Bbase + kk;
        cp16(sA0[buf], A + (size_t)r0 * DIM + cb0 * 8);
        cp16(sA1[buf], A + (size_t)r1 * DIM + cb1 * 8);
        cp16(sB0[buf], B + (size_t)r0 * CSIZE + cb0 * 8);
        cp16(sB1[buf], B + (size_t)r1 * CSIZE + cb1 * 8);
        asm volatile("cp.async.commit_group;" ::: "memory");
    };

    issue_loads(0, 0);

    for (int i = 0; i < NKITER; ++i) {
        int s = i & 1;
        asm volatile("cp.async.wait_group 0;" ::: "memory");
        __syncthreads();

        if (i < NKITER - 1) issue_loads(i + 1, s ^ 1);

        #pragma unroll
        for (int k2 = 0; k2 < 2; ++k2) {
            wmma::fragment<wmma::matrix_a, 16, 16, 16, __half, wmma::row_major> af[4];
            wmma::fragment<wmma::matrix_b, 16, 16, 16, __half, wmma::col_major> bf[2];
            #pragma unroll
            for (int mi = 0; mi < 4; ++mi)
                wmma::load_matrix_sync(af[mi],
                    &sA[s][(wm * 64 + mi * 16) * LDS_PAD + k2 * 16], LDS_PAD);
            #pragma unroll
            for (int nj = 0; nj < 2; ++nj)
                wmma::load_matrix_sync(bf[nj],
                    &sB[s][(wn * 32 + nj * 16) * LDS_PAD + k2 * 16], LDS_PAD);
            #pragma unroll
            for (int mi = 0; mi < 4; ++mi)
                #pragma unroll
                for (int nj = 0; nj < 2; ++nj)
                    wmma::mma_sync(acc[mi][nj], af[mi], bf[nj], acc[mi][nj]);
        }
        __syncthreads();
    }

    #pragma unroll
    for (int mi = 0; mi < 4; ++mi) {
        #pragma unroll
        for (int nj = 0; nj < 2; ++nj) {
            float* dst = out + (size_t)(m0 + wm * 64 + mi * 16) * DIM
                             + (size_t)c * CSIZE + n0 + wn * 32 + nj * 16;
            wmma::store_matrix_sync(dst, acc[mi][nj], DIM, wmma::mem_row_major);
        }
    }
}

// ---------------------------------------------------------------------------
// Launch: chunk_sinkhorn -> fused (intra-sinkhorn || mix) -> GEMM.
// Single stream; overlap is structural (one kernel, independent block families).
// ---------------------------------------------------------------------------
extern "C" void kernel_launch(void* const* d_in, const int* in_sizes, int n_in,
                              void* d_out, int out_size) {
    const float* x            = (const float*)d_in[0];
    const float* chunk_logits = (const float*)d_in[1];
    const float* intra_logits = (const float*)d_in[2];
    float*       out          = (float*)d_out;

    float*  p;  cudaGetSymbolAddress((void**)&p,  g_p);
    float*  rv; cudaGetSymbolAddress((void**)&rv, g_r);
    float*  cv; cudaGetSymbolAddress((void**)&cv, g_c);
    __half* qh; cudaGetSymbolAddress((void**)&qh, g_qh);
    __half* yh; cudaGetSymbolAddress((void**)&yh, g_yh);

    // 1) 8x8 chunk sinkhorn (mix lane of fused kernel depends on it)
    sinkhorn_chunk_kernel<<<1, 64>>>(chunk_logits, p);

    // 2) fused: intra-sinkhorn (64 persistent blocks) || chunk mix (4096 blocks)
    fused_pre_kernel<<<SINK_BLOCKS + (NROWS * 128) / 512, 512>>>(
        intra_logits, x, p, qh, yh, rv, cv);

    // 3) tensor-core GEMM (fp16 in, fp32 accum): out = Y Q^T per chunk
    dim3 grid(4, NROWS / 128, CHUNKS);
    wmma_gemm_kernel<<<grid, 256>>>(yh, qh, out);
}

// round 13
// speedup vs baseline: 1.0670x; 1.0525x over previous
#include <cuda_runtime.h>
#include <cuda_fp16.h>
#include <mma.h>
#include <math.h>
#include <stdint.h>

using namespace nvcuda;

// Problem constants
#define CHUNKS     8
#define CSIZE      512
#define DIM        4096
#define NROWS      16384
#define INV_TEMP   (1.0f / 0.15f)
#define SINK_ITERS 5

#define NB          8                     // sinkhorn blocks per chunk
#define SINK_BLOCKS (CHUNKS * NB)         // 64

// Scratch (device globals — no runtime allocation allowed)
__device__ float    g_r[CHUNKS * CSIZE];              // row offsets
__device__ float    g_c[CHUNKS * CSIZE];              // col offsets
__device__ unsigned g_barc[CHUNKS];                   // barrier arrive counters
__device__ unsigned g_barg[CHUNKS];                   // barrier generations
__device__ __half   g_qh[CHUNKS * CSIZE * CSIZE];     // 4 MB   Q fp16
__device__ __half   g_yh[(size_t)NROWS * DIM];        // 128 MB Y fp16

// ---------------------------------------------------------------------------
// Per-chunk inter-block barrier (generation-counting, CG grid.sync pattern).
// All NB blocks of a chunk are resident (bid 0..63 dispatched first).
// ---------------------------------------------------------------------------
__device__ __forceinline__ void chunk_barrier(int chunk, unsigned* sgen) {
    __syncthreads();
    if (threadIdx.x == 0) {
        __threadfence();
        unsigned g = *sgen;
        if (atomicAdd(&g_barc[chunk], 1) == NB - 1) {
            g_barc[chunk] = 0;
            __threadfence();
            atomicExch(&g_barg[chunk], g + 1);
        } else {
            while (atomicAdd(&g_barg[chunk], 0) <= g) __nanosleep(64);
        }
        *sgen = g + 1;
    }
    __syncthreads();
}

// ---------------------------------------------------------------------------
// Fused pre-GEMM kernel (the ONLY pre-GEMM launch).
//   blocks [0, 64):  persistent intra-sinkhorn, 8 blocks/chunk, vector form:
//                      r_i = LSE_j(L_ij - c_j); c_j = LSE_i(L_ij - r_i)
//                    (no max-shift: args bounded); final pass emits
//                    qh = exp(L - r - c) in fp16.
//   blocks [64, ..): compute 8x8 chunk perm P in-block (redundant, ~1.5us),
//                    then chunk mix y = P @ x -> fp16 yh (streaming hints).
// ---------------------------------------------------------------------------
__global__ __launch_bounds__(512, 2)
void fused_pre_kernel(const float* __restrict__ intra,
                      const float* __restrict__ x,
                      const float* __restrict__ chunkL,
                      __half* __restrict__ qh,
                      __half* __restrict__ yh,
                      float* __restrict__ rg_, float* __restrict__ cg_) {
    __shared__ float smem[512];
    __shared__ unsigned sgen;

    if (blockIdx.x < SINK_BLOCKS) {
        // ------------------ intra-sinkhorn lane ------------------
        const int chunk = blockIdx.x >> 3;
        const int sub   = blockIdx.x & 7;
        const int tid   = threadIdx.x;
        const int warp  = tid >> 5;
        const int lane  = tid & 31;
        const float* L = intra + (size_t)chunk * CSIZE * CSIZE;
        float* rv = rg_ + chunk * CSIZE;
        float* cv = cg_ + chunk * CSIZE;

        if (tid == 0) sgen = atomicAdd(&g_barg[chunk], 0);
        __syncthreads();

        for (int it = 0; it < SINK_ITERS; ++it) {
            // r-pass: rows [sub*64, sub*64+64), 4 rows per warp
            #pragma unroll
            for (int k = 0; k < 4; ++k) {
                int row = sub * 64 + warp * 4 + k;
                const float4* lp = (const float4*)(L + (size_t)row * CSIZE);
                float s = 0.0f;
                #pragma unroll
                for (int q = 0; q < 4; ++q) {
                    float4 t = lp[lane + q * 32];
                    if (it > 0) {
                        float4 cc = ((const float4*)cv)[lane + q * 32];
                        s += __expf(t.x * INV_TEMP - cc.x)
                           + __expf(t.y * INV_TEMP - cc.y)
                           + __expf(t.z * INV_TEMP - cc.z)
                           + __expf(t.w * INV_TEMP - cc.w);
                    } else {
                        s += __expf(t.x * INV_TEMP) + __expf(t.y * INV_TEMP)
                           + __expf(t.z * INV_TEMP) + __expf(t.w * INV_TEMP);
                    }
                }
                #pragma unroll
                for (int o = 16; o > 0; o >>= 1)
                    s += __shfl_xor_sync(0xFFFFFFFFu, s, o);
                if (lane == 0) rv[row] = __logf(s);
            }
            chunk_barrier(chunk, &sgen);

            // c-pass: cols [sub*64, sub*64+64), 8 rowgroups x 64 cols
            {
                int col = sub * 64 + (tid & 63);
                int rgp = tid >> 6;                  // 0..7
                float s = 0.0f;
                for (int row = rgp; row < CSIZE; row += 8)
                    s += __expf(L[(size_t)row * CSIZE + col] * INV_TEMP - rv[row]);
                smem[tid] = s;
                __syncthreads();
                if (tid < 64) {
                    float tot = smem[tid];
                    #pragma unroll
                    for (int j = 1; j < 8; ++j) tot += smem[tid + j * 64];
                    cv[sub * 64 + tid] = __logf(tot);
                }
                __syncthreads();
            }
            chunk_barrier(chunk, &sgen);
        }

        // emit qh = exp(L*invT - r - c), rows [sub*64, +64), coalesced by row
        float cj = cv[tid];
        __half* qbase = qh + (size_t)chunk * CSIZE * CSIZE;
        for (int row = sub * 64; row < sub * 64 + 64; ++row) {
            float rr = rv[row];
            qbase[(size_t)row * CSIZE + tid] = __float2half(
                __expf(L[(size_t)row * CSIZE + tid] * INV_TEMP - rr - cj));
        }
    } else {
        // ------------------ chunk-mix lane ------------------
        // Step 1: compute 8x8 chunk-perm P in-block (threads 0..63 active).
        const int t = threadIdx.x;
        float v = 0.0f;
        const int pr = t >> 3, pc = t & 7;
        if (t < 64) v = chunkL[t] * INV_TEMP;

        for (int it = 0; it < SINK_ITERS; ++it) {
            if (t < 64) smem[t] = v;
            __syncthreads();
            if (t < 64) {
                float mx = -1e30f;
                #pragma unroll
                for (int j = 0; j < 8; ++j) mx = fmaxf(mx, smem[pr * 8 + j]);
                float sm = 0.0f;
                #pragma unroll
                for (int j = 0; j < 8; ++j) sm += expf(smem[pr * 8 + j] - mx);
                v -= mx + logf(sm);
            }
            __syncthreads();
            if (t < 64) smem[t] = v;
            __syncthreads();
            if (t < 64) {
                float mx = -1e30f;
                #pragma unroll
                for (int j = 0; j < 8; ++j) mx = fmaxf(mx, smem[j * 8 + pc]);
                float sm = 0.0f;
                #pragma unroll
                for (int j = 0; j < 8; ++j) sm += expf(smem[j * 8 + pc] - mx);
                v -= mx + logf(sm);
            }
            __syncthreads();
        }
        if (t < 64) smem[t] = expf(v);     // P now lives in smem[0..63]
        __syncthreads();

        // Step 2: mix (streaming loads/stores).
        int id = (blockIdx.x - SINK_BLOCKS) * 512 + t;
        int b  = id >> 7;
        int d4 = id & 127;

        const float4* xb = (const float4*)(x + (size_t)b * DIM) + d4;

        float4 xv[8];
        #pragma unroll
        for (int j = 0; j < 8; ++j) xv[j] = __ldcs(xb + (size_t)j * 128);

        #pragma unroll
        for (int i = 0; i < 8; ++i) {
            float4 acc = make_float4(0.f, 0.f, 0.f, 0.f);
            #pragma unroll
            for (int j = 0; j < 8; ++j) {
                float w = smem[i * 8 + j];
                acc.x += w * xv[j].x;
                acc.y += w * xv[j].y;
                acc.z += w * xv[j].z;
                acc.w += w * xv[j].w;
            }
            __half2 h01 = __floats2half2_rn(acc.x, acc.y);
            __half2 h23 = __floats2half2_rn(acc.z, acc.w);
            size_t e = (size_t)b * DIM + (size_t)i * CSIZE + (size_t)d4 * 4;
            __stcs(((__half2*)yh) + (e >> 1),       h01);
            __stcs(((__half2*)yh) + (e >> 1) + 1,   h23);
        }
    }
}

// ---------------------------------------------------------------------------
// WMMA (HMMA) GEMM, fp16 in / fp32 accum: per CTA 128x128 tile, K = 512.
// Double-buffered cp.async, 8 warps (2M x 4N), warp tile 64x32.
// (Measured at ~94% of the legacy-HMMA issue ceiling — do not touch.)
// ---------------------------------------------------------------------------
#define LDS_PAD 40
#define NKITER  16

__device__ __forceinline__ void cp16(uint32_t dst, const void* src) {
    asm volatile("cp.async.cg.shared.global [%0], [%1], 16;" :: "r"(dst), "l"(src));
}

__global__ __launch_bounds__(256, 2)
void wmma_gemm_kernel(const __half* __restrict__ yh,
                      const __half* __restrict__ qh,
                      float* __restrict__ out) {
    __shared__ __half sA[2][128 * LDS_PAD];
    __shared__ __half sB[2][128 * LDS_PAD];

    const int c  = blockIdx.z;
    const int m0 = blockIdx.y * 128;
    const int n0 = blockIdx.x * 128;
    const int tid = threadIdx.x;
    const int wid = tid >> 5;
    const int wm  = wid & 1;
    const int wn  = wid >> 1;

    wmma::fragment<wmma::accumulator, 16, 16, 16, float> acc[4][2];
    #pragma unroll
    for (int i = 0; i < 4; ++i)
        #pragma unroll
        for (int j = 0; j < 2; ++j) wmma::fill_fragment(acc[i][j], 0.0f);

    const int r0  = (tid + 0)   >> 2;
    const int cb0 = (tid + 0)   & 3;
    const int r1  = (tid + 256) >> 2;
    const int cb1 = (tid + 256) & 3;

    uint32_t sA0[2], sA1[2], sB0[2], sB1[2];
    #pragma unroll
    for (int b = 0; b < 2; ++b) {
        sA0[b] = (uint32_t)__cvta_generic_to_shared(&sA[b][r0 * LDS_PAD + cb0 * 8]);
        sA1[b] = (uint32_t)__cvta_generic_to_shared(&sA[b][r1 * LDS_PAD + cb1 * 8]);
        sB0[b] = (uint32_t)__cvta_generic_to_shared(&sB[b][r0 * LDS_PAD + cb0 * 8]);
        sB1[b] = (uint32_t)__cvta_generic_to_shared(&sB[b][r1 * LDS_PAD + cb1 * 8]);
    }

    const __half* Abase = yh + (size_t)m0 * DIM + (size_t)c * CSIZE;
    const __half* Bbase = qh + (size_t)c * CSIZE * CSIZE + (size_t)n0 * CSIZE;

    auto issue_loads = [&](int i, int buf) {
        int kk = i << 5;
        const __half* A = Abase + kk;
        const __half* B = Bbase + kk;
        cp16(sA0[buf], A + (size_t)r0 * DIM + cb0 * 8);
        cp16(sA1[buf], A + (size_t)r1 * DIM + cb1 * 8);
        cp16(sB0[buf], B + (size_t)r0 * CSIZE + cb0 * 8);
        cp16(sB1[buf], B + (size_t)r1 * CSIZE + cb1 * 8);
        asm volatile("cp.async.commit_group;" ::: "memory");
    };

    issue_loads(0, 0);

    for (int i = 0; i < NKITER; ++i) {
        int s = i & 1;
        asm volatile("cp.async.wait_group 0;" ::: "memory");
        __syncthreads();

        if (i < NKITER - 1) issue_loads(i + 1, s ^ 1);

        #pragma unroll
        for (int k2 = 0; k2 < 2; ++k2) {
            wmma::fragment<wmma::matrix_a, 16, 16, 16, __half, wmma::row_major> af[4];
            wmma::fragment<wmma::matrix_b, 16, 16, 16, __half, wmma::col_major> bf[2];
            #pragma unroll
            for (int mi = 0; mi < 4; ++mi)
                wmma::load_matrix_sync(af[mi],
                    &sA[s][(wm * 64 + mi * 16) * LDS_PAD + k2 * 16], LDS_PAD);
            #pragma unroll
            for (int nj = 0; nj < 2; ++nj)
                wmma::load_matrix_sync(bf[nj],
                    &sB[s][(wn * 32 + nj * 16) * LDS_PAD + k2 * 16], LDS_PAD);
            #pragma unroll
            for (int mi = 0; mi < 4; ++mi)
                #pragma unroll
                for (int nj = 0; nj < 2; ++nj)
                    wmma::mma_sync(acc[mi][nj], af[mi], bf[nj], acc[mi][nj]);
        }
        __syncthreads();
    }

    #pragma unroll
    for (int mi = 0; mi < 4; ++mi) {
        #pragma unroll
        for (int nj = 0; nj < 2; ++nj) {
            float* dst = out + (size_t)(m0 + wm * 64 + mi * 16) * DIM
                             + (size_t)c * CSIZE + n0 + wn * 32 + nj * 16;
            wmma::store_matrix_sync(dst, acc[mi][nj], DIM, wmma::mem_row_major);
        }
    }
}

// ---------------------------------------------------------------------------
// Launch: fused (chunk-perm + intra-sinkhorn || mix) -> GEMM. Two launches.
// ---------------------------------------------------------------------------
extern "C" void kernel_launch(void* const* d_in, const int* in_sizes, int n_in,
                              void* d_out, int out_size) {
    const float* x            = (const float*)d_in[0];
    const float* chunk_logits = (const float*)d_in[1];
    const float* intra_logits = (const float*)d_in[2];
    float*       out          = (float*)d_out;

    float*  rv; cudaGetSymbolAddress((void**)&rv, g_r);
    float*  cv; cudaGetSymbolAddress((void**)&cv, g_c);
    __half* qh; cudaGetSymbolAddress((void**)&qh, g_qh);
    __half* yh; cudaGetSymbolAddress((void**)&yh, g_yh);

    // 1) fused: intra-sinkhorn (64 persistent blocks) || chunk-perm + mix
    fused_pre_kernel<<<SINK_BLOCKS + (NROWS * 128) / 512, 512>>>(
        intra_logits, x, chunk_logits, qh, yh, rv, cv);

    // 2) tensor-core GEMM (fp16 in, fp32 accum): out = Y Q^T per chunk
    dim3 grid(4, NROWS / 128, CHUNKS);
    wmma_gemm_kernel<<<grid, 256>>>(yh, qh, out);
}

// round 14
// speedup vs baseline: 1.1106x; 1.0409x over previous
#include <cuda_runtime.h>
#include <cuda_fp16.h>
#include <mma.h>
#include <math.h>
#include <stdint.h>

using namespace nvcuda;

// Problem constants
#define CHUNKS     8
#define CSIZE      512
#define DIM        4096
#define NROWS      16384
#define INV_TEMP   (1.0f / 0.15f)
#define SINK_ITERS 5

#define NB          8                     // sinkhorn blocks per chunk
#define SINK_BLOCKS (CHUNKS * NB)         // 64

// Scratch (device globals — no runtime allocation allowed)
__device__ float    g_r[CHUNKS * CSIZE];              // row offsets
__device__ float    g_c[CHUNKS * CSIZE];              // col offsets
__device__ unsigned g_barc[CHUNKS];                   // barrier arrive counters
__device__ unsigned g_barg[CHUNKS];                   // barrier generations
__device__ __half   g_qh[CHUNKS * CSIZE * CSIZE];     // 4 MB   Q fp16
__device__ __half   g_yh[(size_t)NROWS * DIM];        // 128 MB Y fp16

// ---------------------------------------------------------------------------
// Per-chunk inter-block barrier (generation-counting, CG grid.sync pattern).
// ---------------------------------------------------------------------------
__device__ __forceinline__ void chunk_barrier(int chunk, unsigned* sgen) {
    __syncthreads();
    if (threadIdx.x == 0) {
        __threadfence();
        unsigned g = *sgen;
        if (atomicAdd(&g_barc[chunk], 1) == NB - 1) {
            g_barc[chunk] = 0;
            __threadfence();
            atomicExch(&g_barg[chunk], g + 1);
        } else {
            while (atomicAdd(&g_barg[chunk], 0) <= g) __nanosleep(64);
        }
        *sgen = g + 1;
    }
    __syncthreads();
}

// ---------------------------------------------------------------------------
// Fused pre-GEMM kernel (unchanged from round 13 — proven).
//   blocks [0, 64):  persistent intra-sinkhorn (vector form, per-chunk barrier)
//   blocks [64, ..): in-block 8x8 chunk-perm sinkhorn, then streaming mix.
// ---------------------------------------------------------------------------
__global__ __launch_bounds__(512, 2)
void fused_pre_kernel(const float* __restrict__ intra,
                      const float* __restrict__ x,
                      const float* __restrict__ chunkL,
                      __half* __restrict__ qh,
                      __half* __restrict__ yh,
                      float* __restrict__ rg_, float* __restrict__ cg_) {
    __shared__ float smem[512];
    __shared__ unsigned sgen;

    if (blockIdx.x < SINK_BLOCKS) {
        const int chunk = blockIdx.x >> 3;
        const int sub   = blockIdx.x & 7;
        const int tid   = threadIdx.x;
        const int warp  = tid >> 5;
        const int lane  = tid & 31;
        const float* L = intra + (size_t)chunk * CSIZE * CSIZE;
        float* rv = rg_ + chunk * CSIZE;
        float* cv = cg_ + chunk * CSIZE;

        if (tid == 0) sgen = atomicAdd(&g_barg[chunk], 0);
        __syncthreads();

        for (int it = 0; it < SINK_ITERS; ++it) {
            #pragma unroll
            for (int k = 0; k < 4; ++k) {
                int row = sub * 64 + warp * 4 + k;
                const float4* lp = (const float4*)(L + (size_t)row * CSIZE);
                float s = 0.0f;
                #pragma unroll
                for (int q = 0; q < 4; ++q) {
                    float4 t = lp[lane + q * 32];
                    if (it > 0) {
                        float4 cc = ((const float4*)cv)[lane + q * 32];
                        s += __expf(t.x * INV_TEMP - cc.x)
                           + __expf(t.y * INV_TEMP - cc.y)
                           + __expf(t.z * INV_TEMP - cc.z)
                           + __expf(t.w * INV_TEMP - cc.w);
                    } else {
                        s += __expf(t.x * INV_TEMP) + __expf(t.y * INV_TEMP)
                           + __expf(t.z * INV_TEMP) + __expf(t.w * INV_TEMP);
                    }
                }
                #pragma unroll
                for (int o = 16; o > 0; o >>= 1)
                    s += __shfl_xor_sync(0xFFFFFFFFu, s, o);
                if (lane == 0) rv[row] = __logf(s);
            }
            chunk_barrier(chunk, &sgen);

            {
                int col = sub * 64 + (tid & 63);
                int rgp = tid >> 6;
                float s = 0.0f;
                for (int row = rgp; row < CSIZE; row += 8)
                    s += __expf(L[(size_t)row * CSIZE + col] * INV_TEMP - rv[row]);
                smem[tid] = s;
                __syncthreads();
                if (tid < 64) {
                    float tot = smem[tid];
                    #pragma unroll
                    for (int j = 1; j < 8; ++j) tot += smem[tid + j * 64];
                    cv[sub * 64 + tid] = __logf(tot);
                }
                __syncthreads();
            }
            chunk_barrier(chunk, &sgen);
        }

        float cj = cv[tid];
        __half* qbase = qh + (size_t)chunk * CSIZE * CSIZE;
        for (int row = sub * 64; row < sub * 64 + 64; ++row) {
            float rr = rv[row];
            qbase[(size_t)row * CSIZE + tid] = __float2half(
                __expf(L[(size_t)row * CSIZE + tid] * INV_TEMP - rr - cj));
        }
    } else {
        const int t = threadIdx.x;
        float v = 0.0f;
        const int pr = t >> 3, pc = t & 7;
        if (t < 64) v = chunkL[t] * INV_TEMP;

        for (int it = 0; it < SINK_ITERS; ++it) {
            if (t < 64) smem[t] = v;
            __syncthreads();
            if (t < 64) {
                float mx = -1e30f;
                #pragma unroll
                for (int j = 0; j < 8; ++j) mx = fmaxf(mx, smem[pr * 8 + j]);
                float sm = 0.0f;
                #pragma unroll
                for (int j = 0; j < 8; ++j) sm += expf(smem[pr * 8 + j] - mx);
                v -= mx + logf(sm);
            }
            __syncthreads();
            if (t < 64) smem[t] = v;
            __syncthreads();
            if (t < 64) {
                float mx = -1e30f;
                #pragma unroll
                for (int j = 0; j < 8; ++j) mx = fmaxf(mx, smem[j * 8 + pc]);
                float sm = 0.0f;
                #pragma unroll
                for (int j = 0; j < 8; ++j) sm += expf(smem[j * 8 + pc] - mx);
                v -= mx + logf(sm);
            }
            __syncthreads();
        }
        if (t < 64) smem[t] = expf(v);
        __syncthreads();

        int id = (blockIdx.x - SINK_BLOCKS) * 512 + t;
        int b  = id >> 7;
        int d4 = id & 127;

        const float4* xb = (const float4*)(x + (size_t)b * DIM) + d4;

        float4 xv[8];
        #pragma unroll
        for (int j = 0; j < 8; ++j) xv[j] = __ldcs(xb + (size_t)j * 128);

        #pragma unroll
        for (int i = 0; i < 8; ++i) {
            float4 acc = make_float4(0.f, 0.f, 0.f, 0.f);
            #pragma unroll
            for (int j = 0; j < 8; ++j) {
                float w = smem[i * 8 + j];
                acc.x += w * xv[j].x;
                acc.y += w * xv[j].y;
                acc.z += w * xv[j].z;
                acc.w += w * xv[j].w;
            }
            __half2 h01 = __floats2half2_rn(acc.x, acc.y);
            __half2 h23 = __floats2half2_rn(acc.z, acc.w);
            size_t e = (size_t)b * DIM + (size_t)i * CSIZE + (size_t)d4 * 4;
            __stcs(((__half2*)yh) + (e >> 1),       h01);
            __stcs(((__half2*)yh) + (e >> 1) + 1,   h23);
        }
    }
}

// ---------------------------------------------------------------------------
// WMMA (HMMA) GEMM, fp16 in / fp32 accum. CTA 128x128, K-step 32.
// NEW: 4-stage cp.async ring (3 K-steps ahead), ONE __syncthreads per K-iter.
// ncu showed tensor pipe only 45% active with 2-stage/2-sync: latency-bound.
// ---------------------------------------------------------------------------
#define LDS_PAD 40                       // 80 B padded row stride
#define NKITER  16                       // 512 / 32
#define NSTAGE  4
#define MAT_ELEMS (128 * LDS_PAD)        // elems per A or B stage (5120)
#define STAGE_ELEMS (2 * MAT_ELEMS)      // A+B per stage
#define GEMM_SMEM (NSTAGE * STAGE_ELEMS * 2)  // 81920 bytes

__device__ __forceinline__ void cp16(uint32_t dst, const void* src) {
    asm volatile("cp.async.cg.shared.global [%0], [%1], 16;" :: "r"(dst), "l"(src));
}

__global__ __launch_bounds__(256, 2)
void wmma_gemm_kernel(const __half* __restrict__ yh,
                      const __half* __restrict__ qh,
                      float* __restrict__ out) {
    extern __shared__ __half smem[];

    const int c  = blockIdx.z;
    const int m0 = blockIdx.y * 128;
    const int n0 = blockIdx.x * 128;
    const int tid = threadIdx.x;
    const int wid = tid >> 5;
    const int wm  = wid & 1;       // 0..1 -> 64-row slab
    const int wn  = wid >> 1;      // 0..3 -> 32-col slab

    wmma::fragment<wmma::accumulator, 16, 16, 16, float> acc[4][2];
    #pragma unroll
    for (int i = 0; i < 4; ++i)
        #pragma unroll
        for (int j = 0; j < 2; ++j) wmma::fill_fragment(acc[i][j], 0.0f);

    // per-thread load assignment: 512 x 16B units per matrix, 2 per thread
    const int r0  = (tid + 0)   >> 2;
    const int cb0 = (tid + 0)   & 3;
    const int r1  = (tid + 256) >> 2;
    const int cb1 = (tid + 256) & 3;

    uint32_t aD0[NSTAGE], aD1[NSTAGE], bD0[NSTAGE], bD1[NSTAGE];
    #pragma unroll
    for (int s = 0; s < NSTAGE; ++s) {
        __half* sA = smem + s * STAGE_ELEMS;
        __half* sB = sA + MAT_ELEMS;
        aD0[s] = (uint32_t)__cvta_generic_to_shared(sA + r0 * LDS_PAD + cb0 * 8);
        aD1[s] = (uint32_t)__cvta_generic_to_shared(sA + r1 * LDS_PAD + cb1 * 8);
        bD0[s] = (uint32_t)__cvta_generic_to_shared(sB + r0 * LDS_PAD + cb0 * 8);
        bD1[s] = (uint32_t)__cvta_generic_to_shared(sB + r1 * LDS_PAD + cb1 * 8);
    }

    const __half* Abase = yh + (size_t)m0 * DIM + (size_t)c * CSIZE;
    const __half* Bbase = qh + (size_t)c * CSIZE * CSIZE + (size_t)n0 * CSIZE;

    auto issue_loads = [&](int i, int st) {
        int kk = i << 5;
        const __half* A = Abase + kk;
        const __half* B = Bbase + kk;
        cp16(aD0[st], A + (size_t)r0 * DIM + cb0 * 8);
        cp16(aD1[st], A + (size_t)r1 * DIM + cb1 * 8);
        cp16(bD0[st], B + (size_t)r0 * CSIZE + cb0 * 8);
        cp16(bD1[st], B + (size_t)r1 * CSIZE + cb1 * 8);
        asm volatile("cp.async.commit_group;" ::: "memory");
    };

    // prologue: 3 stages in flight
    issue_loads(0, 0);
    issue_loads(1, 1);
    issue_loads(2, 2);

    for (int i = 0; i < NKITER; ++i) {
        const int st = i & 3;

        // wait until stage i has landed (keep up to 2 younger groups pending)
        if (i + 2 < NKITER)
            asm volatile("cp.async.wait_group 2;" ::: "memory");
        else if (i + 2 == NKITER)
            asm volatile("cp.async.wait_group 1;" ::: "memory");
        else
            asm volatile("cp.async.wait_group 0;" ::: "memory");
        __syncthreads();   // single barrier per iter; also frees stage (i-1)%4

        if (i + 3 < NKITER) issue_loads(i + 3, (i + 3) & 3);

        const __half* As = smem + st * STAGE_ELEMS;
        const __half* Bs = As + MAT_ELEMS;

        #pragma unroll
        for (int k2 = 0; k2 < 2; ++k2) {
            wmma::fragment<wmma::matrix_a, 16, 16, 16, __half, wmma::row_major> af[4];
            wmma::fragment<wmma::matrix_b, 16, 16, 16, __half, wmma::col_major> bf[2];
            #pragma unroll
            for (int mi = 0; mi < 4; ++mi)
                wmma::load_matrix_sync(af[mi],
                    &As[(wm * 64 + mi * 16) * LDS_PAD + k2 * 16], LDS_PAD);
            #pragma unroll
            for (int nj = 0; nj < 2; ++nj)
                wmma::load_matrix_sync(bf[nj],
                    &Bs[(wn * 32 + nj * 16) * LDS_PAD + k2 * 16], LDS_PAD);
            #pragma unroll
            for (int mi = 0; mi < 4; ++mi)
                #pragma unroll
                for (int nj = 0; nj < 2; ++nj)
                    wmma::mma_sync(acc[mi][nj], af[mi], bf[nj], acc[mi][nj]);
        }
        // no trailing barrier: next iter's post-wait sync provides the ordering
    }

    // epilogue: direct store to out
    #pragma unroll
    for (int mi = 0; mi < 4; ++mi) {
        #pragma unroll
        for (int nj = 0; nj < 2; ++nj) {
            float* dst = out + (size_t)(m0 + wm * 64 + mi * 16) * DIM
                             + (size_t)c * CSIZE + n0 + wn * 32 + nj * 16;
            wmma::store_matrix_sync(dst, acc[mi][nj], DIM, wmma::mem_row_major);
        }
    }
}

// ---------------------------------------------------------------------------
// Launch: fused (chunk-perm + intra-sinkhorn || mix) -> GEMM. Two launches.
// ---------------------------------------------------------------------------
extern "C" void kernel_launch(void* const* d_in, const int* in_sizes, int n_in,
                              void* d_out, int out_size) {
    const float* x            = (const float*)d_in[0];
    const float* chunk_logits = (const float*)d_in[1];
    const float* intra_logits = (const float*)d_in[2];
    float*       out          = (float*)d_out;

    float*  rv; cudaGetSymbolAddress((void**)&rv, g_r);
    float*  cv; cudaGetSymbolAddress((void**)&cv, g_c);
    __half* qh; cudaGetSymbolAddress((void**)&qh, g_qh);
    __half* yh; cudaGetSymbolAddress((void**)&yh, g_yh);

    // 1) fused: intra-sinkhorn (64 persistent blocks) || chunk-perm + mix
    fused_pre_kernel<<<SINK_BLOCKS + (NROWS * 128) / 512, 512>>>(
        intra_logits, x, chunk_logits, qh, yh, rv, cv);

    // 2) tensor-core GEMM, 4-stage pipeline (dynamic smem, 2 CTA/SM)
    cudaFuncSetAttribute(wmma_gemm_kernel,
                         cudaFuncAttributeMaxDynamicSharedMemorySize, GEMM_SMEM);
    dim3 grid(4, NROWS / 128, CHUNKS);
    wmma_gemm_kernel<<<grid, 256, GEMM_SMEM>>>(yh, qh, out);
}